// round 12
// baseline (speedup 1.0000x reference)
#include <cuda_runtime.h>
#include <math.h>

// WaveNet collapsed to the last-sample 32-dim recurrence (k=0 tap only).
// R12: residual FOLDED into the next layer's filter/gate at pack time:
//   A_L = -2 F_{L+1} (R_L + I),  B_L = -G_{L+1} (R_L + I)
//   => u_L = act(W_L v_L), v_{L+1} = u_L   (single GEMV pair per layer,
//      no residual GEMV, one syncwarp per layer, ring 2/3 smaller)
//   skip += S_L u_L (fp32 — issue-cheaper than fp16 per R11 evidence)
//   out = end2 @ relu(end1 @ relu(skip) + b1) + b2
//
//  1) wn_pack : blocks 0..39 do the per-layer 32x32x32 fold-matmul (smem);
//               blocks 40..167 copy skipT/end1T (float4 remap) + start conv.
//  2) wn_main : grid=8 (batch), 256 thr, 64KB smem weight ring.
//     warp 0    : folded recurrence from SMEM (LDS.128 + f32x2 FMAs).
//     warps 1-7 : batched ring producers + fp32 skip GEMM one chunk behind;
//                 then the fp32 end1/end2 head.

#define NL   40
#define RC   32
#define SC   256
#define CIN  6
#define T_IN 8192
#define FULLM 0xffffffffu

#define CH   4                 // layers per chunk
#define NCH  (NL / CH)         // 10 chunks
#define LW   512               // float4 per layer (2048 floats: A@0 B@256)
#define CW   (CH * LW)         // float4 per chunk = 2048
#define RING_BYTES (2 * CW * 16)   // 65536

typedef unsigned long long u64;

__device__ float g_pk[NL * 2048];            // folded A/B, fp32, 328 KB
__device__ float g_skipT4[(NL * RC) * SC];   // [kg][c][4kk] fp32, 1.31 MB
__device__ float g_end1T4[SC * SC];          // [jg][c][4jj] fp32, 256 KB
__device__ float g_xs0[8 * RC];

__device__ __forceinline__ void fma2(u64& d, u64 a, u64 b) {
    asm("fma.rn.f32x2 %0, %1, %2, %3;" : "=l"(d) : "l"(a), "l"(b), "l"(d));
}
__device__ __forceinline__ void add2(u64& d, u64 a, u64 b) {
    asm("add.rn.f32x2 %0, %1, %2;" : "=l"(d) : "l"(a), "l"(b));
}
__device__ __forceinline__ float2 upk(u64 v) {
    float2 r; asm("mov.b64 {%0, %1}, %2;" : "=f"(r.x), "=f"(r.y) : "l"(v));
    return r;
}

// ---------------------------------------------------------------- pack
// blocks 0..39  : fold-matmul for layer slot L (256 threads)
// blocks 40..167: grid-stride copy of skipT4 / end1T4 / xs0
__global__ __launch_bounds__(256, 1)
void wn_pack(const float* __restrict__ x,
             const float* __restrict__ start_w,
             const float* __restrict__ filter_w,
             const float* __restrict__ gate_w,
             const float* __restrict__ res_w,
             const float* __restrict__ skip_w,
             const float* __restrict__ end1_w)
{
    const int blk = blockIdx.x;
    const int tid = threadIdx.x;

    if (blk < NL) {
        // ---- per-layer fold: slot L uses F/G of layer L, R of layer L-1
        const int L = blk;
        __shared__ float Fk[RC][RC];   // -2 * filter k0 taps
        __shared__ float Gk[RC][RC];   // -1 * gate   k0 taps
        __shared__ float Rp[RC][RC];   // R_{L-1} + I

        // load F/G taps: 512 float4 per matrix, 2 per thread
        #pragma unroll
        for (int s = 0; s < 2; s++) {
            const int d  = tid + 256 * s;
            const int i  = d >> 4;
            const int rm = d & 15;
            const float4 fv = *(const float4*)(filter_w + L * 2048 + 4 * d);
            const float4 gv = *(const float4*)(gate_w   + L * 2048 + 4 * d);
            Fk[i][2 * rm]     = -2.f * fv.x;
            Fk[i][2 * rm + 1] = -2.f * fv.z;
            Gk[i][2 * rm]     = -gv.x;
            Gk[i][2 * rm + 1] = -gv.z;
        }
        if (L > 0) {
            // R_{L-1} + I : 256 float4, 1 per thread
            const int d = tid;
            const int k = d >> 3;
            const int j0 = (d & 7) * 4;
            float4 r4 = *(const float4*)(res_w + (L - 1) * 1024 + k * RC + j0);
            if (k >= j0 && k < j0 + 4) (&r4.x)[k - j0] += 1.f;
            *(float4*)&Rp[k][j0] = r4;
        }
        __syncthreads();

        // outputs: 512 float4; thread t -> A(jg,i) and B(jg,i)
        const int jg = tid >> 5;
        const int i  = tid & 31;
        float4 accA, accB;
        if (L == 0) {
            accA = *(const float4*)&Fk[i][4 * jg];
            accB = *(const float4*)&Gk[i][4 * jg];
        } else {
            accA = make_float4(0.f, 0.f, 0.f, 0.f);
            accB = make_float4(0.f, 0.f, 0.f, 0.f);
            #pragma unroll
            for (int k = 0; k < RC; k++) {
                const float4 r4 = *(const float4*)&Rp[k][4 * jg];
                const float fv = Fk[i][k];
                const float gv = Gk[i][k];
                accA.x = fmaf(fv, r4.x, accA.x); accA.y = fmaf(fv, r4.y, accA.y);
                accA.z = fmaf(fv, r4.z, accA.z); accA.w = fmaf(fv, r4.w, accA.w);
                accB.x = fmaf(gv, r4.x, accB.x); accB.y = fmaf(gv, r4.y, accB.y);
                accB.z = fmaf(gv, r4.z, accB.z); accB.w = fmaf(gv, r4.w, accB.w);
            }
        }
        ((float4*)g_pk)[L * LW + jg * 32 + i]       = accA;
        ((float4*)g_pk)[L * LW + 256 + jg * 32 + i] = accB;
    } else {
        // ---- copies: skipT4 (81920 f4), end1T4 (16384 f4), xs0 (256)
        const int NB = NL * RC * SC / 4;   // 81920
        const int NC = SC * SC / 4;        // 16384
        const int total = NB + NC + 8 * RC;
        const int nthr = 128 * 256;
        for (int idx = (blk - NL) * 256 + tid; idx < total; idx += nthr) {
            if (idx < NB) {
                const int kg = idx >> 8;
                const int c  = idx & 255;
                const int L  = kg >> 3;
                const int j0 = (kg & 7) * 4;
                ((float4*)g_skipT4)[idx] =
                    *(const float4*)(skip_w + L * (SC * RC) + c * RC + j0);
            } else if (idx < NB + NC) {
                const int t  = idx - NB;
                const int jg = t >> 8;
                const int c  = t & 255;
                ((float4*)g_end1T4)[t] = *(const float4*)(end1_w + c * SC + 4 * jg);
            } else {
                const int t = idx - NB - NC;
                const int b = t / RC, i = t % RC;
                float s = 0.f;
                #pragma unroll
                for (int ci = 0; ci < CIN; ci++)
                    s += start_w[i * CIN + ci] * x[(b * CIN + ci) * T_IN + (T_IN - 1)];
                g_xs0[b * RC + i] = s;
            }
        }
    }
}

// ---------------------------------------------------------------- main
extern __shared__ float ring[];    // RING_BYTES dynamic smem

__global__ __launch_bounds__(256, 1)
void wn_main(const float* __restrict__ end1_b,
             const float* __restrict__ end2_w,
             const float* __restrict__ end2_b,
             float* __restrict__ out)
{
    const int b    = blockIdx.x;
    const int tid  = threadIdx.x;
    const int lane = tid & 31;
    const int warp = tid >> 5;

    __shared__ __align__(16) float us_all[NL * RC];   // 5.1 KB
    __shared__ __align__(16) float vbuf[2][RC];       // ping-pong state
    __shared__ __align__(16) float hs[SC];
    __shared__ float red8[8];

    // skip-thread channel mapping: warps 1-7 -> c0 in [0,224);
    // warp 1 additionally owns c1 in [224,256).
    const int  c0   = tid - 32;
    const bool dual = (warp == 1);
    const int  c1   = tid + 192;
    float acc0 = 0.f, acc1 = 0.f;

    // prologue: copy chunk 0 (8 float4 each, exact)
    {
        const float4* src = (const float4*)g_pk;
        float4*       dst = (float4*)ring;
        float4 t[8];
        #pragma unroll
        for (int k = 0; k < 8; k++) t[k] = src[tid + 256 * k];
        #pragma unroll
        for (int k = 0; k < 8; k++) dst[tid + 256 * k] = t[k];
    }
    if (warp == 0) vbuf[0][lane] = g_xs0[b * RC + lane];
    __syncthreads();

    for (int q = 0; q <= NCH; q++) {
        if (warp == 0) {
            if (q < NCH) {
                const float4* wc = (const float4*)ring + (q & 1) * CW;
                #pragma unroll
                for (int l = 0; l < CH; l++) {
                    const int L   = q * CH + l;
                    const int par = l & 1;          // CH even => par == L&1
                    const float4* wl = wc + l * LW + lane;

                    u64 fa = 0ull, fb = 0ull, ga = 0ull, gb = 0ull;
                    #pragma unroll
                    for (int jg = 0; jg < 8; jg++) {
                        const ulonglong2 vv = *(const ulonglong2*)&vbuf[par][4 * jg];
                        const ulonglong2 Aw = *(const ulonglong2*)(wl + jg * 32);
                        const ulonglong2 Bw = *(const ulonglong2*)(wl + 256 + jg * 32);
                        fma2(fa, Aw.x, vv.x); fma2(fb, Aw.y, vv.y);
                        fma2(ga, Bw.x, vv.x); fma2(gb, Bw.y, vv.y);
                    }
                    add2(fa, fa, fb);
                    add2(ga, ga, gb);
                    const float2 fp = upk(fa);
                    const float2 gp = upk(ga);
                    const float e1 = __expf(fp.x + fp.y);   // e^{-2f}
                    const float e2 = __expf(gp.x + gp.y);   // e^{-g}
                    // u = tanh(f)*sig(g) = (1-e1)/((1+e1)(1+e2))
                    const float u = __fdividef(1.f - e1, (1.f + e1) * (1.f + e2));
                    us_all[L * RC + lane] = u;
                    vbuf[par ^ 1][lane] = u;
                    __syncwarp();
                }
            }
        } else {
            // producers: batched stage of chunk q+1 into the other ring slot
            if (q + 1 < NCH) {
                const float4* src = (const float4*)g_pk + (q + 1) * CW;
                float4*       dst = (float4*)ring + ((q + 1) & 1) * CW;
                const int t0 = tid - 32;           // 0..223
                float4 t[10];
                #pragma unroll
                for (int k = 0; k < 10; k++) {
                    const int i = t0 + 224 * k;
                    if (i < CW) t[k] = src[i];
                }
                #pragma unroll
                for (int k = 0; k < 10; k++) {
                    const int i = t0 + 224 * k;
                    if (i < CW) dst[i] = t[k];
                }
            }
            // fp32 skip GEMM for chunk q-1: 32 k-groups
            if (q >= 1) {
                const int cq = q - 1;
                const float4* sp = (const float4*)g_skipT4 + (32 * cq) * 256;
                const float*  up = us_all + cq * (CH * RC);
                #pragma unroll
                for (int kg = 0; kg < 32; kg++) {
                    const float4 u4 = *reinterpret_cast<const float4*>(up + 4 * kg);
                    const float4 s4 = sp[kg * 256 + c0];
                    acc0 = fmaf(s4.x, u4.x, fmaf(s4.y, u4.y,
                           fmaf(s4.z, u4.z, fmaf(s4.w, u4.w, acc0))));
                    if (dual) {
                        const float4 s4b = sp[kg * 256 + c1];
                        acc1 = fmaf(s4b.x, u4.x, fmaf(s4b.y, u4.y,
                               fmaf(s4b.z, u4.z, fmaf(s4b.w, u4.w, acc1))));
                    }
                }
            }
        }
        __syncthreads();
    }

    // ---- head (fp32 end1)
    if (warp > 0) {
        hs[c0] = fmaxf(acc0, 0.f);
        if (dual) hs[c1] = fmaxf(acc1, 0.f);
    }
    __syncthreads();

    float o = 0.f;
    if (warp > 0) {
        float e0 = end1_b[c0];
        float e1v = dual ? end1_b[c1] : 0.f;
        const float4* ep = (const float4*)g_end1T4;
        #pragma unroll 8
        for (int jg = 0; jg < 64; jg++) {
            const float4 h4 = *reinterpret_cast<const float4*>(&hs[4 * jg]);
            const float4 a4 = ep[jg * 256 + c0];
            e0 = fmaf(a4.x, h4.x, fmaf(a4.y, h4.y,
                 fmaf(a4.z, h4.z, fmaf(a4.w, h4.w, e0))));
            if (dual) {
                const float4 b4 = ep[jg * 256 + c1];
                e1v = fmaf(b4.x, h4.x, fmaf(b4.y, h4.y,
                      fmaf(b4.z, h4.z, fmaf(b4.w, h4.w, e1v))));
            }
        }
        o = end2_w[c0] * fmaxf(e0, 0.f);
        if (dual) o += end2_w[c1] * fmaxf(e1v, 0.f);
    }
    #pragma unroll
    for (int off = 16; off > 0; off >>= 1)
        o += __shfl_xor_sync(FULLM, o, off);
    if (lane == 0) red8[warp] = o;
    __syncthreads();
    if (tid == 0) {
        float tot = 0.f;
        #pragma unroll
        for (int w = 0; w < 8; w++) tot += red8[w];
        out[b] = tot + end2_b[0];
    }
}

extern "C" void kernel_launch(void* const* d_in, const int* in_sizes, int n_in,
                              void* d_out, int out_size)
{
    const float* x        = (const float*)d_in[0];
    const float* start_w  = (const float*)d_in[1];
    const float* filter_w = (const float*)d_in[2];
    const float* gate_w   = (const float*)d_in[3];
    const float* res_w    = (const float*)d_in[4];
    const float* skip_w   = (const float*)d_in[5];
    const float* end1_w   = (const float*)d_in[6];
    const float* end1_b   = (const float*)d_in[7];
    const float* end2_w   = (const float*)d_in[8];
    const float* end2_b   = (const float*)d_in[9];
    float* out = (float*)d_out;

    cudaFuncSetAttribute(wn_main,
                         cudaFuncAttributeMaxDynamicSharedMemorySize,
                         RING_BYTES);

    wn_pack<<<168, 256>>>(x, start_w, filter_w, gate_w, res_w, skip_w, end1_w);
    wn_main<<<8, 256, RING_BYTES>>>(end1_b, end2_w, end2_b, out);
}